// round 6
// baseline (speedup 1.0000x reference)
#include <cuda_runtime.h>
#include <cuda_bf16.h>
#include <cstdint>

// Problem constants (fixed shapes)
#define L_TOK   4096
#define D_HID   768
#define H_HEAD  12
#define DH      64
#define M2      2048          // L/2
#define OUT_TOK 2049          // 1 unmerged + 2048 dst

// ---------------- device scratch (no allocations allowed) ----------------
__device__ float              g_m[L_TOK * DH];      // normalized metric, 1 MB
__device__ unsigned long long g_best[M2];           // packed (score, ~col)
__device__ int                g_list[M2];           // src rows grouped by dst
__device__ int2               g_hdr[M2];            // (cnt, off) per dst
__device__ int4               g_inl[M2];            // first <=4 src rows per dst

__device__ __forceinline__ unsigned sortable_f32(float f) {
    unsigned u = __float_as_uint(f);
    return (u & 0x80000000u) ? ~u : (u | 0x80000000u);
}

__device__ __forceinline__ unsigned long long pack2(float x) {
    unsigned long long r;
    asm("mov.b64 %0, {%1, %1};" : "=l"(r) : "f"(x));
    return r;
}
__device__ __forceinline__ void ffma2(unsigned long long& d,
                                      unsigned long long a,
                                      unsigned long long b) {
    asm("fma.rn.f32x2 %0, %1, %2, %0;" : "+l"(d) : "l"(a), "l"(b));
}

// ------------------------------------------------------------------------
// K1: metric = mean over heads of key_layer[0], L2-normalized per row.
//     Also initializes g_best.
// grid: 512 blocks x 256 threads (one warp per row)
// ------------------------------------------------------------------------
__global__ void k_metric(const float* __restrict__ key) {
    int gtid = blockIdx.x * blockDim.x + threadIdx.x;
    if (gtid < M2) g_best[gtid] = 0ull;

    int row  = gtid >> 5;                 // one warp per row
    int lane = threadIdx.x & 31;
    if (row < L_TOK) {
        float v0 = 0.f, v1 = 0.f;
        const float* base = key + (size_t)row * DH;
        #pragma unroll
        for (int h = 0; h < H_HEAD; h++) {
            v0 += base[(size_t)h * L_TOK * DH + lane];
            v1 += base[(size_t)h * L_TOK * DH + lane + 32];
        }
        const float invH = 1.0f / (float)H_HEAD;
        v0 *= invH; v1 *= invH;
        float ss = v0 * v0 + v1 * v1;
        #pragma unroll
        for (int o = 16; o; o >>= 1) ss += __shfl_xor_sync(0xffffffffu, ss, o);
        float r = rsqrtf(ss);
        r = r * (1.5f - 0.5f * ss * r * r);   // one Newton step
        g_m[row * DH + lane]      = v0 * r;
        g_m[row * DH + lane + 32] = v1 * r;
    }
}

// ------------------------------------------------------------------------
// K2: argmax_j dot(a_i, b_j) via 2048x2048x64 fp32 GEMM with packed
//     fma.rn.f32x2 (FFMA2).  Tile 64x64, 256 threads, 4x4 microtile.
//     A tile stored duplicated as (a,a) u64 pairs; B pairs come free from
//     contiguous float4.  grid: (32, 32)
// ------------------------------------------------------------------------
#define TS 64
__global__ __launch_bounds__(256) void k_argmax() {
    __shared__ unsigned long long As2[TS * TS];  // (a,a) pairs, K-major, 32 KB
    __shared__ float              Bs [TS * TS];  // K-major, 16 KB

    int tid = threadIdx.x;
    int tx  = tid & 15;               // n direction, 0..15
    int ty  = tid >> 4;               // m direction, 0..15

    int aRow0 = blockIdx.y * TS;      // a-row tile base (in 0..2047)
    int bRow0 = blockIdx.x * TS;      // b-row tile base

    // Load tiles (transpose to K-major).
    int lm = tid & 15;                // m within 16-row group
    int kq = tid >> 4;                // which float4 along K, 0..15
    #pragma unroll
    for (int it = 0; it < 4; it++) {
        int m = it * 16 + lm;
        float4 va = *(const float4*)&g_m[(size_t)(2 * (aRow0 + m)) * DH + kq * 4];
        float4 vb = *(const float4*)&g_m[(size_t)(2 * (bRow0 + m) + 1) * DH + kq * 4];
        As2[(kq * 4 + 0) * TS + m] = pack2(va.x);
        As2[(kq * 4 + 1) * TS + m] = pack2(va.y);
        As2[(kq * 4 + 2) * TS + m] = pack2(va.z);
        As2[(kq * 4 + 3) * TS + m] = pack2(va.w);
        Bs [(kq * 4 + 0) * TS + m] = vb.x;
        Bs [(kq * 4 + 1) * TS + m] = vb.y;
        Bs [(kq * 4 + 2) * TS + m] = vb.z;
        Bs [(kq * 4 + 3) * TS + m] = vb.w;
    }
    __syncthreads();

    unsigned long long acc2[4][2];
    #pragma unroll
    for (int r = 0; r < 4; r++) { acc2[r][0] = 0ull; acc2[r][1] = 0ull; }

    #pragma unroll 16
    for (int k = 0; k < TS; k++) {
        ulonglong2 paA = *(const ulonglong2*)&As2[k * TS + ty * 4];      // (a0,a0),(a1,a1)
        ulonglong2 paB = *(const ulonglong2*)&As2[k * TS + ty * 4 + 2];  // (a2,a2),(a3,a3)
        ulonglong2 pb  = *(const ulonglong2*)&Bs [k * TS + tx * 4];      // (b0,b1),(b2,b3)
        ffma2(acc2[0][0], paA.x, pb.x);  ffma2(acc2[0][1], paA.x, pb.y);
        ffma2(acc2[1][0], paA.y, pb.x);  ffma2(acc2[1][1], paA.y, pb.y);
        ffma2(acc2[2][0], paB.x, pb.x);  ffma2(acc2[2][1], paB.x, pb.y);
        ffma2(acc2[3][0], paB.y, pb.x);  ffma2(acc2[3][1], paB.y, pb.y);
    }

    // Argmax epilogue: per a-row, reduce across the 16 threads (half-warp)
    #pragma unroll
    for (int r = 0; r < 4; r++) {
        int row = aRow0 + ty * 4 + r;
        unsigned long long key = 0ull;
        #pragma unroll
        for (int c2 = 0; c2 < 2; c2++) {
            unsigned lo, hi;
            asm("mov.b64 {%0, %1}, %2;" : "=r"(lo), "=r"(hi) : "l"(acc2[r][c2]));
            float s0 = __uint_as_float(lo), s1 = __uint_as_float(hi);
            int col0 = bRow0 + tx * 4 + 2 * c2;
            unsigned long long k0 =
                ((unsigned long long)sortable_f32(s0) << 32) | (unsigned)(~(unsigned)col0);
            unsigned long long k1 =
                ((unsigned long long)sortable_f32(s1) << 32) | (unsigned)(~(unsigned)(col0 + 1));
            if (k0 > key) key = k0;
            if (k1 > key) key = k1;
        }
        #pragma unroll
        for (int o = 8; o; o >>= 1) {
            unsigned long long other = __shfl_down_sync(0xffffffffu, key, o, 16);
            key = (other > key) ? other : key;
        }
        if (tx == 0) atomicMax(&g_best[row], key);
    }
}

// ------------------------------------------------------------------------
// K3: build CSR (hdr = cnt/off, inline first-4, overflow list).
// Single block, 1024 threads (2 rows per thread).
// ------------------------------------------------------------------------
__global__ __launch_bounds__(1024) void k_build() {
    __shared__ int s_cnt[M2];
    __shared__ int s_off[M2];
    __shared__ int s_list[M2];
    __shared__ int s_part[1024];
    int t = threadIdx.x;
    int i0 = 2 * t, i1 = 2 * t + 1;

    s_cnt[i0] = 0; s_cnt[i1] = 0;
    __syncthreads();

    int dA = (int)(~(unsigned)g_best[i0]) & (M2 - 1);
    int dB = (int)(~(unsigned)g_best[i1]) & (M2 - 1);
    if (i0 >= 1) atomicAdd(&s_cnt[dA], 1);   // src row 0 is unmerged
    atomicAdd(&s_cnt[dB], 1);
    __syncthreads();

    int a = s_cnt[i0], b = s_cnt[i1];
    int pair = a + b;
    s_part[t] = pair;
    __syncthreads();
    // Hillis-Steele inclusive scan over 1024 pair sums
    #pragma unroll
    for (int off = 1; off < 1024; off <<= 1) {
        int v = (t >= off) ? s_part[t - off] : 0;
        __syncthreads();
        s_part[t] += v;
        __syncthreads();
    }
    int excl = s_part[t] - pair;
    s_off[i0] = excl;
    s_off[i1] = excl + a;
    g_hdr[i0] = make_int2(a, excl);
    g_hdr[i1] = make_int2(b, excl + a);
    __syncthreads();

    // reuse s_cnt as fill cursor
    s_cnt[i0] = s_off[i0]; s_cnt[i1] = s_off[i1];
    __syncthreads();
    if (i0 >= 1) { int p = atomicAdd(&s_cnt[dA], 1); s_list[p] = i0; }
    {             int p = atomicAdd(&s_cnt[dB], 1); s_list[p] = i1; }
    __syncthreads();

    // publish list + inline first-4 per dst
    {
        int o0 = s_off[i0], n0 = a;
        int o1 = s_off[i1], n1 = b;
        int4 w;
        w.x = (n0 > 0) ? s_list[o0 + 0] : 0;
        w.y = (n0 > 1) ? s_list[o0 + 1] : 0;
        w.z = (n0 > 2) ? s_list[o0 + 2] : 0;
        w.w = (n0 > 3) ? s_list[o0 + 3] : 0;
        g_inl[i0] = w;
        w.x = (n1 > 0) ? s_list[o1 + 0] : 0;
        w.y = (n1 > 1) ? s_list[o1 + 1] : 0;
        w.z = (n1 > 2) ? s_list[o1 + 2] : 0;
        w.w = (n1 > 3) ? s_list[o1 + 3] : 0;
        g_inl[i1] = w;
        g_list[i0] = s_list[i0];
        g_list[i1] = s_list[i1];
    }
}

// ------------------------------------------------------------------------
// K4: gather-merge. Block j < 2048: out row 1+j = (dst_row + sum srcs)/(1+cnt).
//     Block 2048: unmerged row 0 + attention mask + tome[0].
// grid: 2049 blocks x 192 threads (768 floats = 192 float4)
// ------------------------------------------------------------------------
__global__ __launch_bounds__(192) void k_merge(const float* __restrict__ hidden,
                                               const float* __restrict__ tome,
                                               float* __restrict__ out) {
    float* out_tok  = out;                              // 2049 x 768
    float* out_mask = out + (size_t)OUT_TOK * D_HID;    // 2049
    float* out_tome = out_mask + OUT_TOK;               // 2049
    int b = blockIdx.x, t = threadIdx.x;

    if (b == M2) {   // unmerged row 0, mask, tome[0]
        ((float4*)out_tok)[t] = ((const float4*)hidden)[t];
        for (int i = t; i < OUT_TOK; i += 192) out_mask[i] = 0.0f;
        if (t == 0) out_tome[0] = tome[0];
        return;
    }

    int j   = b;
    int2 hdr = g_hdr[j];
    int cnt = hdr.x, off = hdr.y;
    int4 inl = g_inl[j];
    float inv = 1.0f / (1.0f + (float)cnt);

    float4 acc = ((const float4*)&hidden[(size_t)(2 * j + 1) * D_HID])[t];

    float4 v0 = {0,0,0,0}, v1 = {0,0,0,0}, v2 = {0,0,0,0}, v3 = {0,0,0,0};
    if (cnt > 0) v0 = ((const float4*)&hidden[(size_t)(2 * inl.x) * D_HID])[t];
    if (cnt > 1) v1 = ((const float4*)&hidden[(size_t)(2 * inl.y) * D_HID])[t];
    if (cnt > 2) v2 = ((const float4*)&hidden[(size_t)(2 * inl.z) * D_HID])[t];
    if (cnt > 3) v3 = ((const float4*)&hidden[(size_t)(2 * inl.w) * D_HID])[t];
    acc.x += (v0.x + v1.x) + (v2.x + v3.x);
    acc.y += (v0.y + v1.y) + (v2.y + v3.y);
    acc.z += (v0.z + v1.z) + (v2.z + v3.z);
    acc.w += (v0.w + v1.w) + (v2.w + v3.w);

    for (int s = 4; s < cnt; s++) {      // rare overflow path
        int i0 = g_list[off + s];
        float4 v = ((const float4*)&hidden[(size_t)(2 * i0) * D_HID])[t];
        acc.x += v.x; acc.y += v.y; acc.z += v.z; acc.w += v.w;
    }
    acc.x *= inv; acc.y *= inv; acc.z *= inv; acc.w *= inv;
    ((float4*)&out_tok[(size_t)(1 + j) * D_HID])[t] = acc;

    if (t == 0) {
        float ts = tome[2 * j + 1];
        if (cnt > 0) ts += tome[2 * inl.x];
        if (cnt > 1) ts += tome[2 * inl.y];
        if (cnt > 2) ts += tome[2 * inl.z];
        if (cnt > 3) ts += tome[2 * inl.w];
        for (int q = 4; q < cnt; q++) ts += tome[2 * g_list[off + q]];
        out_tome[1 + j] = ts;
    }
}

// ------------------------------------------------------------------------
extern "C" void kernel_launch(void* const* d_in, const int* in_sizes, int n_in,
                              void* d_out, int out_size) {
    // inputs (metadata order): hidden_states, attention_mask,
    //                          self_attention_scores, key_layer, tome_size
    const float* hidden = (const float*)d_in[0];
    const float* key    = (const float*)d_in[3];
    const float* tome   = (const float*)d_in[4];
    float* out = (float*)d_out;

    k_metric<<<512, 256>>>(key);
    k_argmax<<<dim3(M2 / TS, M2 / TS), 256>>>();
    k_build<<<1, 1024>>>();
    k_merge<<<OUT_TOK, 192>>>(hidden, tome, out);
}

// round 7
// speedup vs baseline: 1.2600x; 1.2600x over previous
#include <cuda_runtime.h>
#include <cuda_bf16.h>
#include <cstdint>

// Problem constants (fixed shapes)
#define L_TOK   4096
#define D_HID   768
#define H_HEAD  12
#define DH      64
#define M2      2048          // L/2
#define OUT_TOK 2049          // 1 unmerged + 2048 dst

// ---------------- device scratch (no allocations allowed) ----------------
__device__ float              g_m[L_TOK * DH];      // normalized metric, 1 MB
__device__ unsigned long long g_best[M2];           // packed (score, ~col)
__device__ int                g_cnt[M2];            // #srcs per dst
__device__ int                g_off[M2];            // CSR offsets
__device__ int                g_list[M2];           // src rows grouped by dst

__device__ __forceinline__ unsigned sortable_f32(float f) {
    unsigned u = __float_as_uint(f);
    return (u & 0x80000000u) ? ~u : (u | 0x80000000u);
}
__device__ __forceinline__ unsigned long long pack2(float x) {
    unsigned long long r;
    asm("mov.b64 %0, {%1, %1};" : "=l"(r) : "f"(x));
    return r;
}
__device__ __forceinline__ void ffma2(unsigned long long& d,
                                      unsigned long long a,
                                      unsigned long long b) {
    asm("fma.rn.f32x2 %0, %1, %2, %0;" : "+l"(d) : "l"(a), "l"(b));
}

// ------------------------------------------------------------------------
// K1: metric = mean over heads of key_layer[0], L2-normalized per row.
//     Also initializes g_best.  grid: 512 x 256 (one warp per row)
// ------------------------------------------------------------------------
__global__ void k_metric(const float* __restrict__ key) {
    int gtid = blockIdx.x * blockDim.x + threadIdx.x;
    if (gtid < M2) g_best[gtid] = 0ull;

    int row  = gtid >> 5;
    int lane = threadIdx.x & 31;
    if (row < L_TOK) {
        float v0 = 0.f, v1 = 0.f;
        const float* base = key + (size_t)row * DH;
        #pragma unroll
        for (int h = 0; h < H_HEAD; h++) {
            v0 += base[(size_t)h * L_TOK * DH + lane];
            v1 += base[(size_t)h * L_TOK * DH + lane + 32];
        }
        const float invH = 1.0f / (float)H_HEAD;
        v0 *= invH; v1 *= invH;
        float ss = v0 * v0 + v1 * v1;
        #pragma unroll
        for (int o = 16; o; o >>= 1) ss += __shfl_xor_sync(0xffffffffu, ss, o);
        float r = rsqrtf(ss);
        r = r * (1.5f - 0.5f * ss * r * r);   // one Newton step
        g_m[row * DH + lane]      = v0 * r;
        g_m[row * DH + lane + 32] = v1 * r;
    }
}

// ------------------------------------------------------------------------
// K2: argmax_j dot(a_i, b_j) — 2048x2048x64 fp32 GEMM with FFMA2.
// Tile 128x128, 256 threads, 8x8 microtile. A duplicated into (a,a) pairs
// in REGISTERS (mov.b64, ALU pipe); B pairs reinterpreted from contiguous
// smem float4 for free.  64 KB dynamic smem.  grid: (16, 16)
// ------------------------------------------------------------------------
#define BM 128
__global__ __launch_bounds__(256) void k_argmax() {
    extern __shared__ float smem[];
    float* As = smem;              // [64][128] K-major: As[k*128 + m]
    float* Bs = smem + 64 * BM;    // [64][128]

    int tid = threadIdx.x;
    int tx  = tid & 15;            // col group (8 cols each)
    int ty  = tid >> 4;            // row group (8 rows each)

    int aRow0 = blockIdx.y * BM;
    int bRow0 = blockIdx.x * BM;

    // Load tiles, transposing to K-major. 8 float4 per thread per matrix.
    int lm  = tid & 31;            // m within 32-row group
    int kq8 = tid >> 5;            // 0..7
    #pragma unroll
    for (int it = 0; it < 4; it++) {
        int m = it * 32 + lm;
        const float* arow = &g_m[(size_t)(2 * (aRow0 + m)) * DH];
        const float* brow = &g_m[(size_t)(2 * (bRow0 + m) + 1) * DH];
        #pragma unroll
        for (int half = 0; half < 2; half++) {
            int kq = kq8 + half * 8;           // 0..15
            float4 va = *(const float4*)&arow[kq * 4];
            float4 vb = *(const float4*)&brow[kq * 4];
            As[(kq * 4 + 0) * BM + m] = va.x;
            As[(kq * 4 + 1) * BM + m] = va.y;
            As[(kq * 4 + 2) * BM + m] = va.z;
            As[(kq * 4 + 3) * BM + m] = va.w;
            Bs[(kq * 4 + 0) * BM + m] = vb.x;
            Bs[(kq * 4 + 1) * BM + m] = vb.y;
            Bs[(kq * 4 + 2) * BM + m] = vb.z;
            Bs[(kq * 4 + 3) * BM + m] = vb.w;
        }
    }
    __syncthreads();

    unsigned long long acc2[8][4];
    #pragma unroll
    for (int r = 0; r < 8; r++)
        #pragma unroll
        for (int c = 0; c < 4; c++) acc2[r][c] = 0ull;

    #pragma unroll 8
    for (int k = 0; k < 64; k++) {
        float4 a0 = *(const float4*)&As[k * BM + ty * 8];
        float4 a1 = *(const float4*)&As[k * BM + ty * 8 + 4];
        ulonglong2 b01 = *(const ulonglong2*)&Bs[k * BM + tx * 8];      // (b0,b1),(b2,b3)
        ulonglong2 b23 = *(const ulonglong2*)&Bs[k * BM + tx * 8 + 4];  // (b4,b5),(b6,b7)
        unsigned long long ap[8];
        ap[0] = pack2(a0.x); ap[1] = pack2(a0.y);
        ap[2] = pack2(a0.z); ap[3] = pack2(a0.w);
        ap[4] = pack2(a1.x); ap[5] = pack2(a1.y);
        ap[6] = pack2(a1.z); ap[7] = pack2(a1.w);
        #pragma unroll
        for (int r = 0; r < 8; r++) {
            ffma2(acc2[r][0], ap[r], b01.x);
            ffma2(acc2[r][1], ap[r], b01.y);
            ffma2(acc2[r][2], ap[r], b23.x);
            ffma2(acc2[r][3], ap[r], b23.y);
        }
    }

    // Argmax epilogue: per a-row, reduce across the 16 tx threads (half-warp)
    #pragma unroll
    for (int r = 0; r < 8; r++) {
        int row = aRow0 + ty * 8 + r;
        unsigned long long key = 0ull;
        #pragma unroll
        for (int c2 = 0; c2 < 4; c2++) {
            unsigned lo, hi;
            asm("mov.b64 {%0, %1}, %2;" : "=r"(lo), "=r"(hi) : "l"(acc2[r][c2]));
            float s0 = __uint_as_float(lo), s1 = __uint_as_float(hi);
            int col0 = bRow0 + tx * 8 + 2 * c2;
            unsigned long long k0 =
                ((unsigned long long)sortable_f32(s0) << 32) | (unsigned)(~(unsigned)col0);
            unsigned long long k1 =
                ((unsigned long long)sortable_f32(s1) << 32) | (unsigned)(~(unsigned)(col0 + 1));
            if (k0 > key) key = k0;
            if (k1 > key) key = k1;
        }
        #pragma unroll
        for (int o = 8; o; o >>= 1) {
            unsigned long long other = __shfl_down_sync(0xffffffffu, key, o, 16);
            key = (other > key) ? other : key;
        }
        if (tx == 0) atomicMax(&g_best[row], key);
    }
}

// ------------------------------------------------------------------------
// K3: build CSR (counts, offsets, src lists).  1 block x 1024 threads.
// ------------------------------------------------------------------------
__global__ __launch_bounds__(1024) void k_build() {
    __shared__ int s_cnt[M2];
    __shared__ int s_off[M2];
    __shared__ int s_part[1024];
    int t = threadIdx.x;
    int i0 = 2 * t, i1 = 2 * t + 1;

    s_cnt[i0] = 0; s_cnt[i1] = 0;
    __syncthreads();

    int dA = (int)(~(unsigned)g_best[i0]) & (M2 - 1);
    int dB = (int)(~(unsigned)g_best[i1]) & (M2 - 1);
    if (i0 >= 1) atomicAdd(&s_cnt[dA], 1);   // src row 0 is unmerged
    atomicAdd(&s_cnt[dB], 1);
    __syncthreads();

    int a = s_cnt[i0], b = s_cnt[i1];
    int pair = a + b;
    s_part[t] = pair;
    __syncthreads();
    #pragma unroll
    for (int off = 1; off < 1024; off <<= 1) {
        int v = (t >= off) ? s_part[t - off] : 0;
        __syncthreads();
        s_part[t] += v;
        __syncthreads();
    }
    int excl = s_part[t] - pair;
    s_off[i0] = excl;
    s_off[i1] = excl + a;
    g_cnt[i0] = a;  g_cnt[i1] = b;
    g_off[i0] = excl; g_off[i1] = excl + a;
    __syncthreads();

    s_cnt[i0] = s_off[i0]; s_cnt[i1] = s_off[i1];   // fill cursors
    __syncthreads();
    if (i0 >= 1) { int p = atomicAdd(&s_cnt[dA], 1); g_list[p] = i0; }
    {             int p = atomicAdd(&s_cnt[dB], 1); g_list[p] = i1; }
}

// ------------------------------------------------------------------------
// K4: gather-merge. Block j < 2048: out row 1+j = (dst_row + sum srcs)/(1+cnt).
//     Block 2048: unmerged row 0 + attention mask + tome[0].
// grid: 2049 x 192
// ------------------------------------------------------------------------
__global__ __launch_bounds__(192) void k_merge(const float* __restrict__ hidden,
                                               const float* __restrict__ tome,
                                               float* __restrict__ out) {
    float* out_tok  = out;                              // 2049 x 768
    float* out_mask = out + (size_t)OUT_TOK * D_HID;    // 2049
    float* out_tome = out_mask + OUT_TOK;               // 2049
    int b = blockIdx.x, t = threadIdx.x;

    if (b == M2) {   // unmerged row 0, mask, tome[0]
        ((float4*)out_tok)[t] = ((const float4*)hidden)[t];
        for (int i = t; i < OUT_TOK; i += 192) out_mask[i] = 0.0f;
        if (t == 0) out_tome[0] = tome[0];
        return;
    }

    int j   = b;
    int cnt = g_cnt[j];
    int off = g_off[j];
    float inv = 1.0f / (1.0f + (float)cnt);

    float4 acc = ((const float4*)&hidden[(size_t)(2 * j + 1) * D_HID])[t];

    int s = 0;
    for (; s + 4 <= cnt; s += 4) {
        int i0 = g_list[off + s + 0];
        int i1 = g_list[off + s + 1];
        int i2 = g_list[off + s + 2];
        int i3 = g_list[off + s + 3];
        float4 v0 = ((const float4*)&hidden[(size_t)(2 * i0) * D_HID])[t];
        float4 v1 = ((const float4*)&hidden[(size_t)(2 * i1) * D_HID])[t];
        float4 v2 = ((const float4*)&hidden[(size_t)(2 * i2) * D_HID])[t];
        float4 v3 = ((const float4*)&hidden[(size_t)(2 * i3) * D_HID])[t];
        acc.x += v0.x + v1.x + v2.x + v3.x;
        acc.y += v0.y + v1.y + v2.y + v3.y;
        acc.z += v0.z + v1.z + v2.z + v3.z;
        acc.w += v0.w + v1.w + v2.w + v3.w;
    }
    for (; s < cnt; s++) {
        int i0 = g_list[off + s];
        float4 v0 = ((const float4*)&hidden[(size_t)(2 * i0) * D_HID])[t];
        acc.x += v0.x; acc.y += v0.y; acc.z += v0.z; acc.w += v0.w;
    }
    acc.x *= inv; acc.y *= inv; acc.z *= inv; acc.w *= inv;
    ((float4*)&out_tok[(size_t)(1 + j) * D_HID])[t] = acc;

    if (t == 0) {
        float ts = tome[2 * j + 1];
        for (int q = 0; q < cnt; q++) ts += tome[2 * g_list[off + q]];
        out_tome[1 + j] = ts;
    }
}

// ------------------------------------------------------------------------
extern "C" void kernel_launch(void* const* d_in, const int* in_sizes, int n_in,
                              void* d_out, int out_size) {
    const float* hidden = (const float*)d_in[0];
    const float* key    = (const float*)d_in[3];
    const float* tome   = (const float*)d_in[4];
    float* out = (float*)d_out;

    static int smem_set = 0;
    if (!smem_set) {
        cudaFuncSetAttribute(k_argmax,
                             cudaFuncAttributeMaxDynamicSharedMemorySize, 65536);
        smem_set = 1;
    }

    k_metric<<<512, 256>>>(key);
    k_argmax<<<dim3(M2 / BM, M2 / BM), 256, 65536>>>();
    k_build<<<1, 1024>>>();
    k_merge<<<OUT_TOK, 192>>>(hidden, tome, out);
}

// round 8
// speedup vs baseline: 1.2973x; 1.0296x over previous
#include <cuda_runtime.h>
#include <cuda_bf16.h>
#include <cstdint>

// Problem constants (fixed shapes)
#define L_TOK   4096
#define D_HID   768
#define H_HEAD  12
#define DH      64
#define M2      2048          // L/2
#define OUT_TOK 2049          // 1 unmerged + 2048 dst

// ---------------- device scratch (no allocations allowed) ----------------
__device__ float              g_m[L_TOK * DH];      // normalized metric, 1 MB
__device__ unsigned long long g_best[M2];           // packed (score, ~col)
__device__ int                g_cnt[M2];            // #srcs per dst
__device__ int                g_off[M2];            // CSR offsets
__device__ int                g_list[M2];           // src rows grouped by dst

__device__ __forceinline__ unsigned sortable_f32(float f) {
    unsigned u = __float_as_uint(f);
    return (u & 0x80000000u) ? ~u : (u | 0x80000000u);
}
__device__ __forceinline__ unsigned long long pack2(float x) {
    unsigned long long r;
    asm("mov.b64 %0, {%1, %1};" : "=l"(r) : "f"(x));
    return r;
}
__device__ __forceinline__ void ffma2(unsigned long long& d,
                                      unsigned long long a,
                                      unsigned long long b) {
    asm("fma.rn.f32x2 %0, %1, %2, %0;" : "+l"(d) : "l"(a), "l"(b));
}

// ------------------------------------------------------------------------
// K1: metric = mean over heads of key_layer[0], L2-normalized per row.
//     Also initializes g_best.  grid: 512 x 256 (one warp per row)
// ------------------------------------------------------------------------
__global__ void k_metric(const float* __restrict__ key) {
    int gtid = blockIdx.x * blockDim.x + threadIdx.x;
    if (gtid < M2) g_best[gtid] = 0ull;

    int row  = gtid >> 5;
    int lane = threadIdx.x & 31;
    if (row < L_TOK) {
        float v0 = 0.f, v1 = 0.f;
        const float* base = key + (size_t)row * DH;
        #pragma unroll
        for (int h = 0; h < H_HEAD; h++) {
            v0 += base[(size_t)h * L_TOK * DH + lane];
            v1 += base[(size_t)h * L_TOK * DH + lane + 32];
        }
        const float invH = 1.0f / (float)H_HEAD;
        v0 *= invH; v1 *= invH;
        float ss = v0 * v0 + v1 * v1;
        #pragma unroll
        for (int o = 16; o; o >>= 1) ss += __shfl_xor_sync(0xffffffffu, ss, o);
        float r = rsqrtf(ss);
        r = r * (1.5f - 0.5f * ss * r * r);   // one Newton step
        g_m[row * DH + lane]      = v0 * r;
        g_m[row * DH + lane + 32] = v1 * r;
    }
}

// ------------------------------------------------------------------------
// K2: argmax_j dot(a_i, b_j) — 2048x2048x64 fp32 GEMM with FFMA2.
// Tile 128x128, 256 threads, 8x8 microtile. A duplicated into (a,a) pairs
// in REGISTERS; B pairs reinterpreted from contiguous smem float4.
// 64 KB dynamic smem.  grid: (16, 16)
// ------------------------------------------------------------------------
#define BM 128
__global__ __launch_bounds__(256) void k_argmax() {
    extern __shared__ float smem[];
    float* As = smem;              // [64][128] K-major: As[k*128 + m]
    float* Bs = smem + 64 * BM;    // [64][128]

    int tid = threadIdx.x;
    int tx  = tid & 15;            // col group (8 cols each)
    int ty  = tid >> 4;            // row group (8 rows each)

    int aRow0 = blockIdx.y * BM;
    int bRow0 = blockIdx.x * BM;

    // Load tiles, transposing to K-major. 8 float4 per thread per matrix.
    int lm  = tid & 31;            // m within 32-row group
    int kq8 = tid >> 5;            // 0..7
    #pragma unroll
    for (int it = 0; it < 4; it++) {
        int m = it * 32 + lm;
        const float* arow = &g_m[(size_t)(2 * (aRow0 + m)) * DH];
        const float* brow = &g_m[(size_t)(2 * (bRow0 + m) + 1) * DH];
        #pragma unroll
        for (int half = 0; half < 2; half++) {
            int kq = kq8 + half * 8;           // 0..15
            float4 va = *(const float4*)&arow[kq * 4];
            float4 vb = *(const float4*)&brow[kq * 4];
            As[(kq * 4 + 0) * BM + m] = va.x;
            As[(kq * 4 + 1) * BM + m] = va.y;
            As[(kq * 4 + 2) * BM + m] = va.z;
            As[(kq * 4 + 3) * BM + m] = va.w;
            Bs[(kq * 4 + 0) * BM + m] = vb.x;
            Bs[(kq * 4 + 1) * BM + m] = vb.y;
            Bs[(kq * 4 + 2) * BM + m] = vb.z;
            Bs[(kq * 4 + 3) * BM + m] = vb.w;
        }
    }
    __syncthreads();

    unsigned long long acc2[8][4];
    #pragma unroll
    for (int r = 0; r < 8; r++)
        #pragma unroll
        for (int c = 0; c < 4; c++) acc2[r][c] = 0ull;

    #pragma unroll 8
    for (int k = 0; k < 64; k++) {
        float4 a0 = *(const float4*)&As[k * BM + ty * 8];
        float4 a1 = *(const float4*)&As[k * BM + ty * 8 + 4];
        ulonglong2 b01 = *(const ulonglong2*)&Bs[k * BM + tx * 8];      // (b0,b1),(b2,b3)
        ulonglong2 b23 = *(const ulonglong2*)&Bs[k * BM + tx * 8 + 4];  // (b4,b5),(b6,b7)
        unsigned long long ap[8];
        ap[0] = pack2(a0.x); ap[1] = pack2(a0.y);
        ap[2] = pack2(a0.z); ap[3] = pack2(a0.w);
        ap[4] = pack2(a1.x); ap[5] = pack2(a1.y);
        ap[6] = pack2(a1.z); ap[7] = pack2(a1.w);
        #pragma unroll
        for (int r = 0; r < 8; r++) {
            ffma2(acc2[r][0], ap[r], b01.x);
            ffma2(acc2[r][1], ap[r], b01.y);
            ffma2(acc2[r][2], ap[r], b23.x);
            ffma2(acc2[r][3], ap[r], b23.y);
        }
    }

    // Argmax epilogue: per a-row, reduce across the 16 tx threads (half-warp)
    #pragma unroll
    for (int r = 0; r < 8; r++) {
        int row = aRow0 + ty * 8 + r;
        unsigned long long key = 0ull;
        #pragma unroll
        for (int c2 = 0; c2 < 4; c2++) {
            unsigned lo, hi;
            asm("mov.b64 {%0, %1}, %2;" : "=r"(lo), "=r"(hi) : "l"(acc2[r][c2]));
            float s0 = __uint_as_float(lo), s1 = __uint_as_float(hi);
            int col0 = bRow0 + tx * 8 + 2 * c2;
            unsigned long long k0 =
                ((unsigned long long)sortable_f32(s0) << 32) | (unsigned)(~(unsigned)col0);
            unsigned long long k1 =
                ((unsigned long long)sortable_f32(s1) << 32) | (unsigned)(~(unsigned)(col0 + 1));
            if (k0 > key) key = k0;
            if (k1 > key) key = k1;
        }
        #pragma unroll
        for (int o = 8; o; o >>= 1) {
            unsigned long long other = __shfl_down_sync(0xffffffffu, key, o, 16);
            key = (other > key) ? other : key;
        }
        if (tx == 0) atomicMax(&g_best[row], key);
    }
}

// ------------------------------------------------------------------------
// K3: build CSR (counts, offsets, src lists).  1 block x 1024 threads.
// Warp-shuffle scan (2 block syncs instead of 20).
// ------------------------------------------------------------------------
__global__ __launch_bounds__(1024) void k_build() {
    __shared__ int s_cnt[M2];
    __shared__ int s_off[M2];
    __shared__ int s_wsum[32];
    int t    = threadIdx.x;
    int lane = t & 31;
    int wid  = t >> 5;
    int i0 = 2 * t, i1 = 2 * t + 1;

    s_cnt[i0] = 0; s_cnt[i1] = 0;
    __syncthreads();

    int dA = (int)(~(unsigned)g_best[i0]) & (M2 - 1);
    int dB = (int)(~(unsigned)g_best[i1]) & (M2 - 1);
    if (i0 >= 1) atomicAdd(&s_cnt[dA], 1);   // src row 0 is unmerged
    atomicAdd(&s_cnt[dB], 1);
    __syncthreads();

    int a = s_cnt[i0], b = s_cnt[i1];
    int pair = a + b;

    // inclusive scan: intra-warp shfl, then warp sums scanned by warp 0
    int v = pair;
    #pragma unroll
    for (int o = 1; o < 32; o <<= 1) {
        int n = __shfl_up_sync(0xffffffffu, v, o);
        if (lane >= o) v += n;
    }
    if (lane == 31) s_wsum[wid] = v;
    __syncthreads();
    if (wid == 0) {
        int w = s_wsum[lane];
        #pragma unroll
        for (int o = 1; o < 32; o <<= 1) {
            int n = __shfl_up_sync(0xffffffffu, w, o);
            if (lane >= o) w += n;
        }
        s_wsum[lane] = w;
    }
    __syncthreads();
    int incl = v + ((wid > 0) ? s_wsum[wid - 1] : 0);
    int excl = incl - pair;

    s_off[i0] = excl;
    s_off[i1] = excl + a;
    g_cnt[i0] = a;  g_cnt[i1] = b;
    g_off[i0] = excl; g_off[i1] = excl + a;
    __syncthreads();

    s_cnt[i0] = s_off[i0]; s_cnt[i1] = s_off[i1];   // fill cursors
    __syncthreads();
    if (i0 >= 1) { int p = atomicAdd(&s_cnt[dA], 1); g_list[p] = i0; }
    {             int p = atomicAdd(&s_cnt[dB], 1); g_list[p] = i1; }
}

// ------------------------------------------------------------------------
// K4: gather-merge, 4 dst rows per block for 4x memory-level parallelism.
// Block b < 512: dst rows 4b..4b+3.  Block 512: unmerged row 0 + mask + tome[0].
// grid: 513 x 192
// ------------------------------------------------------------------------
__global__ __launch_bounds__(192) void k_merge(const float* __restrict__ hidden,
                                               const float* __restrict__ tome,
                                               float* __restrict__ out) {
    float* out_tok  = out;                              // 2049 x 768
    float* out_mask = out + (size_t)OUT_TOK * D_HID;    // 2049
    float* out_tome = out_mask + OUT_TOK;               // 2049
    int b = blockIdx.x, t = threadIdx.x;

    if (b == 512) {   // unmerged row 0, mask, tome[0]
        ((float4*)out_tok)[t] = ((const float4*)hidden)[t];
        for (int i = t; i < OUT_TOK; i += 192) out_mask[i] = 0.0f;
        if (t == 0) out_tome[0] = tome[0];
        return;
    }

    int j0 = 4 * b;
    int cnt[4], off[4];
    #pragma unroll
    for (int r = 0; r < 4; r++) { cnt[r] = g_cnt[j0 + r]; off[r] = g_off[j0 + r]; }

    // 4 independent dst loads
    float4 acc[4];
    #pragma unroll
    for (int r = 0; r < 4; r++)
        acc[r] = ((const float4*)&hidden[(size_t)(2 * (j0 + r) + 1) * D_HID])[t];

    // prefetch first two src indices per row (covers cnt<=2 fast path)
    int ia[4], ib[4];
    #pragma unroll
    for (int r = 0; r < 4; r++) ia[r] = (cnt[r] > 0) ? g_list[off[r]]     : -1;
    #pragma unroll
    for (int r = 0; r < 4; r++) ib[r] = (cnt[r] > 1) ? g_list[off[r] + 1] : -1;

    // up to 8 independent src loads in flight
    float4 va[4], vb[4];
    #pragma unroll
    for (int r = 0; r < 4; r++)
        if (ia[r] >= 0) va[r] = ((const float4*)&hidden[(size_t)(2 * ia[r]) * D_HID])[t];
    #pragma unroll
    for (int r = 0; r < 4; r++)
        if (ib[r] >= 0) vb[r] = ((const float4*)&hidden[(size_t)(2 * ib[r]) * D_HID])[t];

    #pragma unroll
    for (int r = 0; r < 4; r++) {
        if (ia[r] >= 0) { acc[r].x += va[r].x; acc[r].y += va[r].y;
                          acc[r].z += va[r].z; acc[r].w += va[r].w; }
        if (ib[r] >= 0) { acc[r].x += vb[r].x; acc[r].y += vb[r].y;
                          acc[r].z += vb[r].z; acc[r].w += vb[r].w; }
        for (int s = 2; s < cnt[r]; s++) {           // rare overflow
            int ix = g_list[off[r] + s];
            float4 v = ((const float4*)&hidden[(size_t)(2 * ix) * D_HID])[t];
            acc[r].x += v.x; acc[r].y += v.y; acc[r].z += v.z; acc[r].w += v.w;
        }
        float inv = 1.0f / (1.0f + (float)cnt[r]);
        acc[r].x *= inv; acc[r].y *= inv; acc[r].z *= inv; acc[r].w *= inv;
        ((float4*)&out_tok[(size_t)(1 + j0 + r) * D_HID])[t] = acc[r];
    }

    if (t < 4) {    // tome sums, one row per thread
        int r = t, j = j0 + r;
        float ts = tome[2 * j + 1];
        for (int q = 0; q < cnt[r]; q++) ts += tome[2 * g_list[off[r] + q]];
        out_tome[1 + j] = ts;
    }
}

// ------------------------------------------------------------------------
extern "C" void kernel_launch(void* const* d_in, const int* in_sizes, int n_in,
                              void* d_out, int out_size) {
    const float* hidden = (const float*)d_in[0];
    const float* key    = (const float*)d_in[3];
    const float* tome   = (const float*)d_in[4];
    float* out = (float*)d_out;

    static int smem_set = 0;
    if (!smem_set) {
        cudaFuncSetAttribute(k_argmax,
                             cudaFuncAttributeMaxDynamicSharedMemorySize, 65536);
        smem_set = 1;
    }

    k_metric<<<512, 256>>>(key);
    k_argmax<<<dim3(M2 / BM, M2 / BM), 256, 65536>>>();
    k_build<<<1, 1024>>>();
    k_merge<<<513, 192>>>(hidden, tome, out);
}